// round 13
// baseline (speedup 1.0000x reference)
#include <cuda_runtime.h>
#include <cuda_fp16.h>
#include <cstdint>

#define BATCH 32768
#define NCH   256
#define FLAT  3072
#define NRED  152
#define NBLK_MOM 128
#define EPSV  1e-5f

// ---------------- device scratch ----------------
__device__ float g_part[NBLK_MOM][NRED];
__device__ float g_wscaled[NCH * 16];
__device__ float g_shift[NCH];
// fc1 weights fp16, TRANSPOSED layout [n][k'], k' = p*256 + c
__device__ __half g_w1t[128 * FLAT];

// ======================= PTX helpers ==================
__device__ __forceinline__ uint32_t smem_u32(const void* p) {
    uint32_t a;
    asm("{ .reg .u64 t; cvta.to.shared.u64 t, %1; cvt.u32.u64 %0, t; }"
        : "=r"(a) : "l"(p));
    return a;
}
#define CP_ASYNC16(dst, src) \
    asm volatile("cp.async.cg.shared.global [%0], [%1], 16;" \
        :: "r"(dst), "l"(src) : "memory")
#define CP_COMMIT() asm volatile("cp.async.commit_group;" ::: "memory")
#define CP_WAIT1()  asm volatile("cp.async.wait_group 1;" ::: "memory")
#define CP_WAIT0()  asm volatile("cp.async.wait_group 0;" ::: "memory")
#define PAIR_BAR(id) asm volatile("bar.sync %0, 64;" :: "r"(id) : "memory")

// NON-trans ldmatrix
__device__ __forceinline__ void ldsm_x4(uint32_t r[4], uint32_t addr) {
    asm volatile("ldmatrix.sync.aligned.m8n8.x4.shared.b16 {%0,%1,%2,%3}, [%4];"
        : "=r"(r[0]), "=r"(r[1]), "=r"(r[2]), "=r"(r[3]) : "r"(addr));
}
__device__ __forceinline__ void mma16816(float& d0, float& d1, float& d2, float& d3,
                                         uint32_t a0, uint32_t a1, uint32_t a2, uint32_t a3,
                                         uint32_t b0, uint32_t b1) {
    asm volatile(
        "mma.sync.aligned.m16n8k16.row.col.f32.f16.f16.f32 "
        "{%0,%1,%2,%3}, {%4,%5,%6,%7}, {%8,%9}, {%0,%1,%2,%3};"
        : "+f"(d0), "+f"(d1), "+f"(d2), "+f"(d3)
        : "r"(a0), "r"(a1), "r"(a2), "r"(a3), "r"(b0), "r"(b1));
}
__device__ __forceinline__ uint32_t f2h2(float a, float b) {
    __half2 h = __floats2half2_rn(a, b);
    return *reinterpret_cast<uint32_t*>(&h);
}

// =========================================================================
// K1: patch moments (proven)
// =========================================================================
__global__ void k_moments(const float* __restrict__ x)
{
    int b = blockIdx.x * 256 + threadIdx.x;
    const float* xb = x + b * 42;
    float xv[42];
#pragma unroll
    for (int i = 0; i < 42; i++) xv[i] = xb[i];

    __shared__ float red[8][NRED];
    int lane = threadIdx.x & 31;
    int warp = threadIdx.x >> 5;

    int idx = 0;
#pragma unroll
    for (int k = 0; k < 16; k++) {
        float s = 0.f;
#pragma unroll
        for (int r = 0; r < 3; r++)
#pragma unroll
            for (int c = 0; c < 4; c++)
                s += xv[(r + (k >> 2)) * 7 + (c + (k & 3))];
#pragma unroll
        for (int o = 16; o; o >>= 1) s += __shfl_xor_sync(0xffffffffu, s, o);
        if (lane == 0) red[warp][idx] = s;
        idx++;
    }
#pragma unroll
    for (int k = 0; k < 16; k++) {
#pragma unroll
        for (int l = k; l < 16; l++) {
            float s = 0.f;
#pragma unroll
            for (int r = 0; r < 3; r++)
#pragma unroll
                for (int c = 0; c < 4; c++)
                    s += xv[(r + (k >> 2)) * 7 + (c + (k & 3))] *
                         xv[(r + (l >> 2)) * 7 + (c + (l & 3))];
#pragma unroll
            for (int o = 16; o; o >>= 1) s += __shfl_xor_sync(0xffffffffu, s, o);
            if (lane == 0) red[warp][idx] = s;
            idx++;
        }
    }
    __syncthreads();
    if (threadIdx.x < NRED) {
        float s = 0.f;
#pragma unroll
        for (int w = 0; w < 8; w++) s += red[w][threadIdx.x];
        g_part[blockIdx.x][threadIdx.x] = s;
    }
}

// =========================================================================
// K2: finalize BN fold (proven)
// =========================================================================
__global__ void k_finalize(const float* __restrict__ conv_w,
                           const float* __restrict__ bn_gamma,
                           const float* __restrict__ bn_beta)
{
    __shared__ float S[NRED];
    int t = threadIdx.x;
    if (t < NRED) {
        float s = 0.f;
        for (int bl = 0; bl < NBLK_MOM; bl++) s += g_part[bl][t];
        S[t] = s * (1.f / (12.f * (float)BATCH));
    }
    __syncthreads();
    if (t < NCH) {
        float w[16];
#pragma unroll
        for (int i = 0; i < 16; i++) w[i] = conv_w[t * 16 + i];
        float mraw = 0.f;
#pragma unroll
        for (int i = 0; i < 16; i++) mraw += w[i] * S[i];
        float q = 0.f;
        int idx = 16;
#pragma unroll
        for (int k = 0; k < 16; k++)
#pragma unroll
            for (int l = k; l < 16; l++) {
                float coef = (k == l) ? (w[k] * w[l]) : (2.f * w[k] * w[l]);
                q += coef * S[idx];
                idx++;
            }
        float var = q - mraw * mraw;
        float a = bn_gamma[t] * rsqrtf(var + EPSV);
#pragma unroll
        for (int i = 0; i < 16; i++) g_wscaled[t * 16 + i] = a * w[i];
        g_shift[t] = bn_beta[t] - a * mraw;
    }
}

// =========================================================================
// K_prep: W1 -> TRANSPOSED [n][k'] fp16.  kp = p*256+c, f = c*12+p.
// =========================================================================
__global__ void k_prep(const float* __restrict__ pw1, const float* __restrict__ vw1)
{
    int n = blockIdx.x;   // 0..127
    for (int kp = threadIdx.x; kp < FLAT; kp += 256) {
        int p = kp >> 8, c = kp & 255;
        int f = c * 12 + p;
        float v = (n < 64) ? pw1[(size_t)f * 64 + n] : vw1[(size_t)f * 64 + (n - 64)];
        g_w1t[(size_t)n * FLAT + kp] = __float2half_rn(v);
    }
}

// =========================================================================
// K4: PAIR-PIPELINED fused kernel — no CTA barrier in the main loop.
// 8 warps = 4 m-slices x 2 n-halves; warp pair = {wm even, wm odd} x wn.
// Each pair owns a private 3-slot cp.async B ring (its n-half, K=64/slot,
// [64 rows n][128B k], kk^(*row&7) swizzle). Sync = 64-thread bar.sync only.
// Per step (K=64) per warp: conv 4 LDSM + 16 HMMA (shift-init) -> pack ->
// fc1 8 LDSM + 64 HMMA.
// Smem: rings 4 x 24576 @0 | Wc [c][k] 48B rows @98304 | shift f2 @110592
// Epilogue reuse: h1 [128][129] @0, h2 [128][65] @66560. SMEM_DYN 111616.
// =========================================================================
#define NITER    48
#define SLOT_B   8192
#define RING_B   (3 * SLOT_B)
#define OFF_WC   98304
#define OFF_SH   110592
#define SMEM_DYN 111616

__global__ __launch_bounds__(256, 2) void k_fused(
    const float* __restrict__ x,
    const float* __restrict__ pb1, const float* __restrict__ vb1,
    const float* __restrict__ pw2, const float* __restrict__ pb2,
    const float* __restrict__ pw3, const float* __restrict__ pb3,
    const float* __restrict__ vw2, const float* __restrict__ vb2,
    const float* __restrict__ vw3, const float* __restrict__ vb3,
    float* __restrict__ out)
{
    extern __shared__ char dyn_pool[];
    __shared__ float biasS[128];

    char* poolA = dyn_pool;
    const uint32_t pool_u = smem_u32(poolA);

    const int tid  = threadIdx.x;
    const int wid  = tid >> 5;
    const int lane = tid & 31;
    const int m0   = blockIdx.x * 128;
    const int wm   = wid & 3;      // m-slice (32 boards)
    const int wn   = wid >> 2;     // n-half (64 outs)

    const int pairid = wn * 2 + (wm >> 1);        // 0..3
    const int pl     = (wm & 1) * 32 + lane;      // pair-local thread 0..63
    const uint32_t ring = pool_u + (uint32_t)pairid * RING_B;

    float2* shiftS2 = (float2*)(poolA + OFF_SH);

    // ---- one-time smem fills ----
    if (tid < 64)       biasS[tid] = pb1[tid];
    else if (tid < 128) biasS[tid] = vb1[tid - 64];
    {   // folded conv weights -> Wc[c][k] fp16, 48B row stride
#pragma unroll
        for (int i = 0; i < 16; i++) {
            int idx = tid + i * 256;
            int k = idx >> 8, c = idx & 255;
            float v = g_wscaled[c * 16 + k];
            uint32_t o = (uint32_t)c * 48 + (uint32_t)(k >> 3) * 16 + (uint32_t)(k & 7) * 2;
            *(__half*)(poolA + OFF_WC + o) = __float2half_rn(v);
        }
    }
    if (tid < 128)
        shiftS2[tid] = make_float2(g_shift[tid * 2], g_shift[tid * 2 + 1]);

    // ---- per-pair B loader: each thread owns row pl of its pair's slot ----
    const __half* gB   = g_w1t + (size_t)(wn * 64 + pl) * FLAT;
    const uint32_t rowoff = (uint32_t)pl * 128;
    const uint32_t rkey   = (uint32_t)(pl & 7);

    // prologue: slots 0 (k 0..63) and 1 (k 64..127)
#pragma unroll
    for (int s = 0; s < 2; s++) {
        const uint32_t sb = ring + s * SLOT_B + rowoff;
        const __half* src = gB + s * 64;
#pragma unroll
        for (int j = 0; j < 8; j++)
            CP_ASYNC16(sb + (((uint32_t)j ^ rkey) << 4), src + j * 8);
        CP_COMMIT();
    }

    // ---- lane constants ----
    const int g     = lane >> 2;
    const int t2    = (lane & 3) * 2;
    const int lrow  = (lane & 7) + ((lane >> 4) & 1) * 8;
    const int khalf = (lane >> 3) & 1;
    const int xo0 = ((t2 >> 2) * 7 + (t2 & 3));
    const int xo1 = (((t2 + 8) >> 2) * 7 + ((t2 + 8) & 3));

    // fc1 B ldsm addressing inside a slot (n-local rows)
    uint32_t fbase[4];
#pragma unroll
    for (int np = 0; np < 4; np++)
        fbase[np] = (uint32_t)(np * 16 + lrow) * 128;
    const uint32_t fkey = (uint32_t)(lrow & 7);
    const uint32_t wlane = (uint32_t)lrow * 48 + (uint32_t)khalf * 16;

    // D accumulators: m32 x n64 per warp
    float d[2][8][4];
#pragma unroll
    for (int mh = 0; mh < 2; mh++)
#pragma unroll
        for (int nt = 0; nt < 8; nt++)
#pragma unroll
            for (int q = 0; q < 4; q++) d[mh][nt][q] = 0.f;

    __syncthreads();   // Wc / shift visible (only CTA barrier before epilogue)

    // x fragments for both m-halves
    uint32_t xhi[2][4];
#pragma unroll
    for (int mh = 0; mh < 2; mh++) {
        const float* xb = x + (size_t)(m0 + wm * 32 + mh * 16) * 42;
        xhi[mh][0] = f2h2(xb[(size_t)g * 42 + xo0],       xb[(size_t)g * 42 + xo0 + 1]);
        xhi[mh][1] = f2h2(xb[(size_t)(g + 8) * 42 + xo0], xb[(size_t)(g + 8) * 42 + xo0 + 1]);
        xhi[mh][2] = f2h2(xb[(size_t)g * 42 + xo1],       xb[(size_t)g * 42 + xo1 + 1]);
        xhi[mh][3] = f2h2(xb[(size_t)(g + 8) * 42 + xo1], xb[(size_t)(g + 8) * 42 + xo1 + 1]);
    }

    // ================= main loop: 48 steps of K=64, pair-local sync ======
#pragma unroll 1
    for (int it = 0; it < NITER; it++) {
        if (it == NITER - 1) { CP_WAIT0(); } else { CP_WAIT1(); }
        PAIR_BAR(pairid + 1);   // slot it%3 visible to both warps;
                                // both warps done reading slot (it-1)%3

        if (it + 2 < NITER) {   // refill slot (it+2)%3
            const uint32_t sb = ring + ((it + 2) % 3) * SLOT_B + rowoff;
            const __half* src = gB + (size_t)(it + 2) * 64;
#pragma unroll
            for (int j = 0; j < 8; j++)
                CP_ASYNC16(sb + (((uint32_t)j ^ rkey) << 4), src + j * 8);
            CP_COMMIT();
        }

        // x rebuild every 4 steps (patch p = it>>2)
        if (it > 0 && (it & 3) == 0) {
            const int p = it >> 2;
            const int po = (p >> 2) * 7 + (p & 3);
#pragma unroll
            for (int mh = 0; mh < 2; mh++) {
                const float* xb = x + (size_t)(m0 + wm * 32 + mh * 16) * 42 + po;
                xhi[mh][0] = f2h2(xb[(size_t)g * 42 + xo0],       xb[(size_t)g * 42 + xo0 + 1]);
                xhi[mh][1] = f2h2(xb[(size_t)(g + 8) * 42 + xo0], xb[(size_t)(g + 8) * 42 + xo0 + 1]);
                xhi[mh][2] = f2h2(xb[(size_t)g * 42 + xo1],       xb[(size_t)g * 42 + xo1 + 1]);
                xhi[mh][3] = f2h2(xb[(size_t)(g + 8) * 42 + xo1], xb[(size_t)(g + 8) * 42 + xo1 + 1]);
            }
        }

        const uint32_t sbB = ring + (it % 3) * SLOT_B;

#pragma unroll
        for (int gg = 0; gg < 2; gg++) {
            const int grp8 = ((it * 2 + gg) & 7);   // channel group 0..7

            float2 sv[4];
#pragma unroll
            for (int nt = 0; nt < 4; nt++)
                sv[nt] = shiftS2[grp8 * 16 + nt * 4 + (t2 >> 1)];

            // ---- conv W loads (non-trans) ----
            uint32_t w0[4], w1[4];
            {
                uint32_t cb = pool_u + OFF_WC + (uint32_t)(grp8 * 32) * 48 + wlane;
                ldsm_x4(w0, cb);
                ldsm_x4(w1, cb + 16 * 48);
            }

            // ---- conv per m-half (accumulators init to shift) ----
            uint32_t afr[2][2][4];
#pragma unroll
            for (int mh = 0; mh < 2; mh++) {
                float cd[4][4];
#pragma unroll
                for (int nt = 0; nt < 4; nt++) {
                    cd[nt][0] = sv[nt].x; cd[nt][1] = sv[nt].y;
                    cd[nt][2] = sv[nt].x; cd[nt][3] = sv[nt].y;
                }
                mma16816(cd[0][0], cd[0][1], cd[0][2], cd[0][3],
                         xhi[mh][0], xhi[mh][1], xhi[mh][2], xhi[mh][3], w0[0], w0[1]);
                mma16816(cd[1][0], cd[1][1], cd[1][2], cd[1][3],
                         xhi[mh][0], xhi[mh][1], xhi[mh][2], xhi[mh][3], w0[2], w0[3]);
                mma16816(cd[2][0], cd[2][1], cd[2][2], cd[2][3],
                         xhi[mh][0], xhi[mh][1], xhi[mh][2], xhi[mh][3], w1[0], w1[1]);
                mma16816(cd[3][0], cd[3][1], cd[3][2], cd[3][3],
                         xhi[mh][0], xhi[mh][1], xhi[mh][2], xhi[mh][3], w1[2], w1[3]);
#pragma unroll
                for (int pr = 0; pr < 2; pr++) {
                    const float* t0 = cd[pr * 2];
                    const float* t1 = cd[pr * 2 + 1];
                    afr[mh][pr][0] = f2h2(fmaxf(t0[0], 0.f), fmaxf(t0[1], 0.f));
                    afr[mh][pr][1] = f2h2(fmaxf(t0[2], 0.f), fmaxf(t0[3], 0.f));
                    afr[mh][pr][2] = f2h2(fmaxf(t1[0], 0.f), fmaxf(t1[1], 0.f));
                    afr[mh][pr][3] = f2h2(fmaxf(t1[2], 0.f), fmaxf(t1[3], 0.f));
                }
            }

            // ---- fc1: 2 k16 chunks; kk = (gg*2+pr)*2+khalf in 0..7 ----
#pragma unroll
            for (int pr = 0; pr < 2; pr++) {
                const uint32_t kk = (uint32_t)((gg * 2 + pr) * 2 + khalf);
#pragma unroll
                for (int np = 0; np < 4; np++) {
                    uint32_t b4[4];
                    ldsm_x4(b4, sbB + fbase[np] + ((kk ^ fkey) << 4));
#pragma unroll
                    for (int mh = 0; mh < 2; mh++) {
                        float* d0 = d[mh][np * 2];
                        float* d1 = d[mh][np * 2 + 1];
                        mma16816(d0[0], d0[1], d0[2], d0[3],
                                 afr[mh][pr][0], afr[mh][pr][1],
                                 afr[mh][pr][2], afr[mh][pr][3], b4[0], b4[1]);
                        mma16816(d1[0], d1[1], d1[2], d1[3],
                                 afr[mh][pr][0], afr[mh][pr][1],
                                 afr[mh][pr][2], afr[mh][pr][3], b4[2], b4[3]);
                    }
                }
            }
        }
    }

    __syncthreads();   // all pairs done; smem reusable

    // ---------------- epilogue ----------------
    float* h1 = (float*)poolA;              // [128][129]
    float* h2 = (float*)(poolA + 66560);    // [128][65]

    {
#pragma unroll
        for (int mh = 0; mh < 2; mh++) {
            const int m = wm * 32 + mh * 16 + g;
#pragma unroll
            for (int nt = 0; nt < 8; nt++) {
                int n = wn * 64 + nt * 8 + t2;
                h1[m * 129 + n]           = fmaxf(d[mh][nt][0] + biasS[n], 0.f);
                h1[m * 129 + n + 1]       = fmaxf(d[mh][nt][1] + biasS[n + 1], 0.f);
                h1[(m + 8) * 129 + n]     = fmaxf(d[mh][nt][2] + biasS[n], 0.f);
                h1[(m + 8) * 129 + n + 1] = fmaxf(d[mh][nt][3] + biasS[n + 1], 0.f);
            }
        }
    }
    __syncthreads();

    // layer2: 128 boards x 64 outs (32 policy | 32 value)
#pragma unroll 1
    for (int it = 0; it < 32; it++) {
        int idx = it * 256 + tid;
        int bd = idx >> 6, o = idx & 63;
        int oo = o & 31;
        const float* h1b  = h1 + bd * 129 + ((o < 32) ? 0 : 64);
        const float* wmat = (o < 32) ? pw2 : vw2;
        float s = (o < 32) ? pb2[oo] : vb2[oo];
#pragma unroll 8
        for (int k = 0; k < 64; k++) s += h1b[k] * wmat[k * 32 + oo];
        h2[bd * 65 + o] = fmaxf(s, 0.f);
    }
    __syncthreads();

    // layer3 + softmax / tanh
    if (tid < 128) {
        int gb = m0 + tid;
        const float* hp = h2 + tid * 65;
        float lg[7];
#pragma unroll
        for (int j = 0; j < 7; j++) {
            float s = pb3[j];
#pragma unroll
            for (int k = 0; k < 32; k++) s += hp[k] * pw3[k * 7 + j];
            lg[j] = s;
        }
        float mx = lg[0];
#pragma unroll
        for (int j = 1; j < 7; j++) mx = fmaxf(mx, lg[j]);
        float se = 0.f;
#pragma unroll
        for (int j = 0; j < 7; j++) { lg[j] = expf(lg[j] - mx); se += lg[j]; }
        float inv = 1.f / se;
#pragma unroll
        for (int j = 0; j < 7; j++) out[(size_t)gb * 7 + j] = lg[j] * inv;

        float v = vb3[0];
#pragma unroll
        for (int k = 0; k < 32; k++) v += hp[32 + k] * vw3[k];
        out[(size_t)BATCH * 7 + gb] = tanhf(v);
    }
}

// =========================================================================
extern "C" void kernel_launch(void* const* d_in, const int* in_sizes, int n_in,
                              void* d_out, int out_size)
{
    const float* x        = (const float*)d_in[0];
    const float* conv_w   = (const float*)d_in[1];
    /* conv_b cancels through batch-norm */
    const float* bn_gamma = (const float*)d_in[3];
    const float* bn_beta  = (const float*)d_in[4];
    const float* pw1 = (const float*)d_in[5];
    const float* pb1 = (const float*)d_in[6];
    const float* pw2 = (const float*)d_in[7];
    const float* pb2 = (const float*)d_in[8];
    const float* pw3 = (const float*)d_in[9];
    const float* pb3 = (const float*)d_in[10];
    const float* vw1 = (const float*)d_in[11];
    const float* vb1 = (const float*)d_in[12];
    const float* vw2 = (const float*)d_in[13];
    const float* vb2 = (const float*)d_in[14];
    const float* vw3 = (const float*)d_in[15];
    const float* vb3 = (const float*)d_in[16];
    float* out = (float*)d_out;

    cudaFuncSetAttribute(k_fused, cudaFuncAttributeMaxDynamicSharedMemorySize, SMEM_DYN);

    k_moments<<<NBLK_MOM, 256>>>(x);
    k_finalize<<<1, 256>>>(conv_w, bn_gamma, bn_beta);
    k_prep<<<128, 256>>>(pw1, vw1);
    k_fused<<<BATCH / 128, 256, SMEM_DYN>>>(x, pb1, vb1, pw2, pb2, pw3, pb3,
                                            vw2, vb2, vw3, vb3, out);
}

// round 14
// speedup vs baseline: 1.3786x; 1.3786x over previous
#include <cuda_runtime.h>
#include <cuda_fp16.h>
#include <cstdint>

#define BATCH 32768
#define NCH   256
#define FLAT  3072
#define NRED  152
#define NBLK_MOM 128
#define EPSV  1e-5f

// ---------------- device scratch ----------------
__device__ float g_part[NBLK_MOM][NRED];
__device__ float g_wscaled[NCH * 16];
__device__ float g_shift[NCH];
// fc1 weights fp16 (hi only), layout [k'][n], k' = p*256 + c
__device__ __half g_w1hi[FLAT * 128];

// ======================= PTX helpers ==================
__device__ __forceinline__ uint32_t smem_u32(const void* p) {
    uint32_t a;
    asm("{ .reg .u64 t; cvta.to.shared.u64 t, %1; cvt.u32.u64 %0, t; }"
        : "=r"(a) : "l"(p));
    return a;
}
#define CP_ASYNC16(dst, src) \
    asm volatile("cp.async.cg.shared.global [%0], [%1], 16;" \
        :: "r"(dst), "l"(src) : "memory")
#define CP_COMMIT() asm volatile("cp.async.commit_group;" ::: "memory")
#define CP_WAIT1()  asm volatile("cp.async.wait_group 1;" ::: "memory")
#define CP_WAIT0()  asm volatile("cp.async.wait_group 0;" ::: "memory")

__device__ __forceinline__ void ldsm_x4t(uint32_t r[4], uint32_t addr) {
    asm volatile("ldmatrix.sync.aligned.m8n8.x4.trans.shared.b16 {%0,%1,%2,%3}, [%4];"
        : "=r"(r[0]), "=r"(r[1]), "=r"(r[2]), "=r"(r[3]) : "r"(addr));
}
__device__ __forceinline__ void mma16816(float& d0, float& d1, float& d2, float& d3,
                                         uint32_t a0, uint32_t a1, uint32_t a2, uint32_t a3,
                                         uint32_t b0, uint32_t b1) {
    asm volatile(
        "mma.sync.aligned.m16n8k16.row.col.f32.f16.f16.f32 "
        "{%0,%1,%2,%3}, {%4,%5,%6,%7}, {%8,%9}, {%0,%1,%2,%3};"
        : "+f"(d0), "+f"(d1), "+f"(d2), "+f"(d3)
        : "r"(a0), "r"(a1), "r"(a2), "r"(a3), "r"(b0), "r"(b1));
}
__device__ __forceinline__ uint32_t f2h2(float a, float b) {
    __half2 h = __floats2half2_rn(a, b);
    return *reinterpret_cast<uint32_t*>(&h);
}

// =========================================================================
// K1 combined: blocks 0..127 -> patch moments; blocks 128..255 -> W1 prep.
// =========================================================================
__global__ void k_front(const float* __restrict__ x,
                        const float* __restrict__ pw1,
                        const float* __restrict__ vw1)
{
    if (blockIdx.x >= NBLK_MOM) {
        // ---- W1 prep: 24 kp-rows per block, coalesced stores ----
        const int b2 = blockIdx.x - NBLK_MOM;     // 0..127
#pragma unroll
        for (int i = 0; i < 12; i++) {
            int idx = i * 256 + threadIdx.x;      // 0..3071
            int kpl = idx >> 7;                   // 0..23
            int n   = idx & 127;
            int kp  = b2 * 24 + kpl;
            int p = kp >> 8, c = kp & 255;
            int f = c * 12 + p;
            float v = (n < 64) ? pw1[(size_t)f * 64 + n]
                               : vw1[(size_t)f * 64 + (n - 64)];
            g_w1hi[(size_t)kp * 128 + n] = __float2half_rn(v);
        }
        return;
    }

    // ---- patch moments (proven) ----
    int b = blockIdx.x * 256 + threadIdx.x;
    const float* xb = x + b * 42;
    float xv[42];
#pragma unroll
    for (int i = 0; i < 42; i++) xv[i] = xb[i];

    __shared__ float red[8][NRED];
    int lane = threadIdx.x & 31;
    int warp = threadIdx.x >> 5;

    int idx = 0;
#pragma unroll
    for (int k = 0; k < 16; k++) {
        float s = 0.f;
#pragma unroll
        for (int r = 0; r < 3; r++)
#pragma unroll
            for (int c = 0; c < 4; c++)
                s += xv[(r + (k >> 2)) * 7 + (c + (k & 3))];
#pragma unroll
        for (int o = 16; o; o >>= 1) s += __shfl_xor_sync(0xffffffffu, s, o);
        if (lane == 0) red[warp][idx] = s;
        idx++;
    }
#pragma unroll
    for (int k = 0; k < 16; k++) {
#pragma unroll
        for (int l = k; l < 16; l++) {
            float s = 0.f;
#pragma unroll
            for (int r = 0; r < 3; r++)
#pragma unroll
                for (int c = 0; c < 4; c++)
                    s += xv[(r + (k >> 2)) * 7 + (c + (k & 3))] *
                         xv[(r + (l >> 2)) * 7 + (c + (l & 3))];
#pragma unroll
            for (int o = 16; o; o >>= 1) s += __shfl_xor_sync(0xffffffffu, s, o);
            if (lane == 0) red[warp][idx] = s;
            idx++;
        }
    }
    __syncthreads();
    if (threadIdx.x < NRED) {
        float s = 0.f;
#pragma unroll
        for (int w = 0; w < 8; w++) s += red[w][threadIdx.x];
        g_part[blockIdx.x][threadIdx.x] = s;
    }
}

// =========================================================================
// K2: finalize BN fold (proven)
// =========================================================================
__global__ void k_finalize(const float* __restrict__ conv_w,
                           const float* __restrict__ bn_gamma,
                           const float* __restrict__ bn_beta)
{
    __shared__ float S[NRED];
    int t = threadIdx.x;
    if (t < NRED) {
        float s = 0.f;
        for (int bl = 0; bl < NBLK_MOM; bl++) s += g_part[bl][t];
        S[t] = s * (1.f / (12.f * (float)BATCH));
    }
    __syncthreads();
    if (t < NCH) {
        float w[16];
#pragma unroll
        for (int i = 0; i < 16; i++) w[i] = conv_w[t * 16 + i];
        float mraw = 0.f;
#pragma unroll
        for (int i = 0; i < 16; i++) mraw += w[i] * S[i];
        float q = 0.f;
        int idx = 16;
#pragma unroll
        for (int k = 0; k < 16; k++)
#pragma unroll
            for (int l = k; l < 16; l++) {
                float coef = (k == l) ? (w[k] * w[l]) : (2.f * w[k] * w[l]);
                q += coef * S[idx];
                idx++;
            }
        float var = q - mraw * mraw;
        float a = bn_gamma[t] * rsqrtf(var + EPSV);
#pragma unroll
        for (int i = 0; i < 16; i++) g_wscaled[t * 16 + i] = a * w[i];
        g_shift[t] = bn_beta[t] - a * mraw;
    }
}

// =========================================================================
// K4: register-dataflow fused kernel (R8 configuration, verbatim).
// Warp owns m16 x n128. Per iter (K=64): conv 8 HMMA -> fc1 64 HMMA.
// Smem: B ring 3x16384 @0 | Wc hi @49152 | shift @57344
//       epilogue reuse: h1 [128][129] f32 @0, h2 [128][65] @66560
// =========================================================================
#define NITER    48
#define OFF_B    0
#define OFF_WC   49152
#define OFF_SH   57344
#define SMEM_DYN 99840

__global__ __launch_bounds__(256, 2) void k_fused(
    const float* __restrict__ x,
    const float* __restrict__ pb1, const float* __restrict__ vb1,
    const float* __restrict__ pw2, const float* __restrict__ pb2,
    const float* __restrict__ pw3, const float* __restrict__ pb3,
    const float* __restrict__ vw2, const float* __restrict__ vb2,
    const float* __restrict__ vw3, const float* __restrict__ vb3,
    float* __restrict__ out)
{
    extern __shared__ char dyn_pool[];
    __shared__ float biasS[128];

    char* poolA = dyn_pool;
    const uint32_t pool_u = smem_u32(poolA);

    const int tid  = threadIdx.x;
    const int wid  = tid >> 5;
    const int lane = tid & 31;
    const int m0   = blockIdx.x * 128;

    float* shiftS = (float*)(poolA + OFF_SH);

    // ---- one-time smem fills ----
    if (tid < 64)       biasS[tid] = pb1[tid];
    else if (tid < 128) biasS[tid] = vb1[tid - 64];
    {   // folded conv weights -> Wc[k][c] fp16 (hi), swizzled rows of 512B
#pragma unroll
        for (int i = 0; i < 16; i++) {
            int idx = tid + i * 256;
            int k = idx >> 8, c = idx & 255;
            float v = g_wscaled[c * 16 + k];
            uint32_t o = (uint32_t)k * 512 + ((((uint32_t)(c >> 3)) ^ (k & 7)) << 4) + (c & 7) * 2;
            *(__half*)(poolA + OFF_WC + o) = __float2half_rn(v);
        }
    }
    shiftS[tid] = g_shift[tid];

    // ---- fc1 B cp.async lanes ----
    const int brow = tid >> 2;
    const int bq   = (tid & 3) * 4;
    const __half* gB = g_w1hi + (size_t)brow * 128 + bq * 8;
    uint32_t oBs[4];
#pragma unroll
    for (int j = 0; j < 4; j++)
        oBs[j] = (uint32_t)brow * 256 + ((((uint32_t)(bq + j)) ^ (brow & 7)) << 4);

    // ---- prologue B(0), B(1) ----
#pragma unroll
    for (int pc = 0; pc < 2; pc++) {
        const uint32_t sb = pool_u + OFF_B + pc * 16384;
        const size_t kofs = (size_t)pc * 64 * 128;
#pragma unroll
        for (int j = 0; j < 4; j++)
            CP_ASYNC16(sb + oBs[j], gB + kofs + j * 8);
        CP_COMMIT();
    }

    // ---- lane constants ----
    const int g    = lane >> 2;
    const int t2   = (lane & 3) * 2;
    const int b_kl = ((lane >> 3) & 1) * 8 + (lane & 7);
    const int b_ng = (lane >> 4);
    const uint32_t key = (uint32_t)(b_kl & 7);

    // constant per-lane swizzle offsets for fc1 B ldsm (np = 0..7)
    uint32_t offnp[8];
#pragma unroll
    for (int np = 0; np < 8; np++)
        offnp[np] = ((((uint32_t)(np * 2 + b_ng)) ^ key) << 4);

    // D accumulators: m16 x n128 per warp
    float d[16][4];
#pragma unroll
    for (int nt = 0; nt < 16; nt++)
#pragma unroll
        for (int q = 0; q < 4; q++) d[nt][q] = 0.f;

    __syncthreads();   // Wc / shift visible

    // x-fragment registers (fp16 hi only)
    uint32_t xhi[4];
    {
        const float* xb = x + (size_t)(m0 + wid * 16) * 42;
        int o0 = ((t2 >> 2) * 7 + (t2 & 3));
        int k1 = t2 + 8;
        int o1 = ((k1 >> 2) * 7 + (k1 & 3));
        xhi[0] = f2h2(xb[(size_t)g * 42 + o0],       xb[(size_t)g * 42 + o0 + 1]);
        xhi[1] = f2h2(xb[(size_t)(g + 8) * 42 + o0], xb[(size_t)(g + 8) * 42 + o0 + 1]);
        xhi[2] = f2h2(xb[(size_t)g * 42 + o1],       xb[(size_t)g * 42 + o1 + 1]);
        xhi[3] = f2h2(xb[(size_t)(g + 8) * 42 + o1], xb[(size_t)(g + 8) * 42 + o1 + 1]);
    }

    // ================= main loop =================
#pragma unroll 1
    for (int it = 0; it < NITER; it++) {
        CP_WAIT1();
        __syncthreads();   // B[it%3] arrived & visible

        if (it + 2 < NITER) {
            const uint32_t sb = pool_u + OFF_B + ((it + 2) % 3) * 16384;
            const size_t kofs = (size_t)(it + 2) * 64 * 128;
#pragma unroll
            for (int j = 0; j < 4; j++)
                CP_ASYNC16(sb + oBs[j], gB + kofs + j * 8);
        }
        CP_COMMIT();

        if (it > 0 && (it & 3) == 0) {
            const int p = it >> 2;
            const float* xb = x + (size_t)(m0 + wid * 16) * 42 + (p >> 2) * 7 + (p & 3);
            int o0 = ((t2 >> 2) * 7 + (t2 & 3));
            int k1 = t2 + 8;
            int o1 = ((k1 >> 2) * 7 + (k1 & 3));
            xhi[0] = f2h2(xb[(size_t)g * 42 + o0],       xb[(size_t)g * 42 + o0 + 1]);
            xhi[1] = f2h2(xb[(size_t)(g + 8) * 42 + o0], xb[(size_t)(g + 8) * 42 + o0 + 1]);
            xhi[2] = f2h2(xb[(size_t)g * 42 + o1],       xb[(size_t)g * 42 + o1 + 1]);
            xhi[3] = f2h2(xb[(size_t)(g + 8) * 42 + o1], xb[(size_t)(g + 8) * 42 + o1 + 1]);
        }

        const uint32_t sbB = pool_u + OFF_B + (it % 3) * 16384;

#pragma unroll
        for (int gg = 0; gg < 2; gg++) {
            const int grp = (it & 3) * 2 + gg;
            const int bg  = grp * 4;

            // ---- conv: batched W loads, then 4 independent MMAs ----
            uint32_t w0[4], w1[4];
            {
                uint32_t wo0 = (uint32_t)b_kl * 512 + ((((uint32_t)(bg + b_ng)) ^ key) << 4);
                uint32_t wo1 = (uint32_t)b_kl * 512 + ((((uint32_t)(bg + 2 + b_ng)) ^ key) << 4);
                ldsm_x4t(w0, pool_u + OFF_WC + wo0);
                ldsm_x4t(w1, pool_u + OFF_WC + wo1);
            }
            float cd[4][4];
#pragma unroll
            for (int nt = 0; nt < 4; nt++)
#pragma unroll
                for (int q = 0; q < 4; q++) cd[nt][q] = 0.f;
            mma16816(cd[0][0], cd[0][1], cd[0][2], cd[0][3],
                     xhi[0], xhi[1], xhi[2], xhi[3], w0[0], w0[1]);
            mma16816(cd[1][0], cd[1][1], cd[1][2], cd[1][3],
                     xhi[0], xhi[1], xhi[2], xhi[3], w0[2], w0[3]);
            mma16816(cd[2][0], cd[2][1], cd[2][2], cd[2][3],
                     xhi[0], xhi[1], xhi[2], xhi[3], w1[0], w1[1]);
            mma16816(cd[3][0], cd[3][1], cd[3][2], cd[3][3],
                     xhi[0], xhi[1], xhi[2], xhi[3], w1[2], w1[3]);

            // ---- pack: shift + ReLU + fp16 -> 2 A-fragments ----
            uint32_t afr[2][4];
#pragma unroll
            for (int pr = 0; pr < 2; pr++) {
                const float* t0 = cd[pr * 2];
                const float* t1 = cd[pr * 2 + 1];
                float2 s0 = *(const float2*)&shiftS[grp * 32 + pr * 16 + t2];
                float2 s1 = *(const float2*)&shiftS[grp * 32 + pr * 16 + 8 + t2];
                afr[pr][0] = f2h2(fmaxf(t0[0] + s0.x, 0.f), fmaxf(t0[1] + s0.y, 0.f));
                afr[pr][1] = f2h2(fmaxf(t0[2] + s0.x, 0.f), fmaxf(t0[3] + s0.y, 0.f));
                afr[pr][2] = f2h2(fmaxf(t1[0] + s1.x, 0.f), fmaxf(t1[1] + s1.y, 0.f));
                afr[pr][3] = f2h2(fmaxf(t1[2] + s1.x, 0.f), fmaxf(t1[3] + s1.y, 0.f));
            }

            // ---- fc1: 2 k16 chunks; per chunk 2 half-batches (4 ldsm + 8 mma) ----
#pragma unroll
            for (int pr = 0; pr < 2; pr++) {
                const uint32_t* af = afr[pr];
                const uint32_t kbase = sbB + (uint32_t)((gg * 2 + pr) * 16 + b_kl) * 256;
#pragma unroll
                for (int h = 0; h < 2; h++) {
                    uint32_t b4[4][4];
                    ldsm_x4t(b4[0], kbase + offnp[h * 4 + 0]);
                    ldsm_x4t(b4[1], kbase + offnp[h * 4 + 1]);
                    ldsm_x4t(b4[2], kbase + offnp[h * 4 + 2]);
                    ldsm_x4t(b4[3], kbase + offnp[h * 4 + 3]);
#pragma unroll
                    for (int j = 0; j < 4; j++) {
                        const int np = h * 4 + j;
                        mma16816(d[np * 2][0], d[np * 2][1], d[np * 2][2], d[np * 2][3],
                                 af[0], af[1], af[2], af[3], b4[j][0], b4[j][1]);
                        mma16816(d[np * 2 + 1][0], d[np * 2 + 1][1],
                                 d[np * 2 + 1][2], d[np * 2 + 1][3],
                                 af[0], af[1], af[2], af[3], b4[j][2], b4[j][3]);
                    }
                }
            }
        }
    }

    CP_WAIT0();
    __syncthreads();

    // ---------------- epilogue ----------------
    float* h1 = (float*)poolA;              // [128][129]
    float* h2 = (float*)(poolA + 66560);    // [128][65]

    {
        const int m = wid * 16 + g;
#pragma unroll
        for (int nt = 0; nt < 16; nt++) {
            int n = nt * 8 + t2;
            h1[m * 129 + n]           = fmaxf(d[nt][0] + biasS[n], 0.f);
            h1[m * 129 + n + 1]       = fmaxf(d[nt][1] + biasS[n + 1], 0.f);
            h1[(m + 8) * 129 + n]     = fmaxf(d[nt][2] + biasS[n], 0.f);
            h1[(m + 8) * 129 + n + 1] = fmaxf(d[nt][3] + biasS[n + 1], 0.f);
        }
    }
    __syncthreads();

    // layer2
#pragma unroll 1
    for (int it = 0; it < 32; it++) {
        int idx = it * 256 + tid;
        int bd = idx >> 6, o = idx & 63;
        int oo = o & 31;
        const float* h1b  = h1 + bd * 129 + ((o < 32) ? 0 : 64);
        const float* wmat = (o < 32) ? pw2 : vw2;
        float s = (o < 32) ? pb2[oo] : vb2[oo];
#pragma unroll 8
        for (int k = 0; k < 64; k++) s += h1b[k] * wmat[k * 32 + oo];
        h2[bd * 65 + o] = fmaxf(s, 0.f);
    }
    __syncthreads();

    // layer3 + softmax / tanh
    if (tid < 128) {
        int gb = m0 + tid;
        const float* hp = h2 + tid * 65;
        float lg[7];
#pragma unroll
        for (int j = 0; j < 7; j++) {
            float s = pb3[j];
#pragma unroll
            for (int k = 0; k < 32; k++) s += hp[k] * pw3[k * 7 + j];
            lg[j] = s;
        }
        float mx = lg[0];
#pragma unroll
        for (int j = 1; j < 7; j++) mx = fmaxf(mx, lg[j]);
        float se = 0.f;
#pragma unroll
        for (int j = 0; j < 7; j++) { lg[j] = expf(lg[j] - mx); se += lg[j]; }
        float inv = 1.f / se;
#pragma unroll
        for (int j = 0; j < 7; j++) out[(size_t)gb * 7 + j] = lg[j] * inv;

        float v = vb3[0];
#pragma unroll
        for (int k = 0; k < 32; k++) v += hp[32 + k] * vw3[k];
        out[(size_t)BATCH * 7 + gb] = tanhf(v);
    }
}

// =========================================================================
extern "C" void kernel_launch(void* const* d_in, const int* in_sizes, int n_in,
                              void* d_out, int out_size)
{
    const float* x        = (const float*)d_in[0];
    const float* conv_w   = (const float*)d_in[1];
    /* conv_b cancels through batch-norm */
    const float* bn_gamma = (const float*)d_in[3];
    const float* bn_beta  = (const float*)d_in[4];
    const float* pw1 = (const float*)d_in[5];
    const float* pb1 = (const float*)d_in[6];
    const float* pw2 = (const float*)d_in[7];
    const float* pb2 = (const float*)d_in[8];
    const float* pw3 = (const float*)d_in[9];
    const float* pb3 = (const float*)d_in[10];
    const float* vw1 = (const float*)d_in[11];
    const float* vb1 = (const float*)d_in[12];
    const float* vw2 = (const float*)d_in[13];
    const float* vb2 = (const float*)d_in[14];
    const float* vw3 = (const float*)d_in[15];
    const float* vb3 = (const float*)d_in[16];
    float* out = (float*)d_out;

    cudaFuncSetAttribute(k_fused, cudaFuncAttributeMaxDynamicSharedMemorySize, SMEM_DYN);

    k_front<<<2 * NBLK_MOM, 256>>>(x, pw1, vw1);
    k_finalize<<<1, 256>>>(conv_w, bn_gamma, bn_beta);
    k_fused<<<BATCH / 128, 256, SMEM_DYN>>>(x, pb1, vb1, pw2, pb2, pw3, pb3,
                                            vw2, vb2, vw3, vb3, out);
}

// round 15
// speedup vs baseline: 1.6580x; 1.2026x over previous
#include <cuda_runtime.h>
#include <cuda_fp16.h>
#include <cstdint>

#define BATCH 32768
#define NCH   256
#define FLAT  3072
#define NRED  152
#define NBLK_MOM 128
#define EPSV  1e-5f

// ---------------- device scratch ----------------
__device__ float g_part[NBLK_MOM][NRED];
__device__ float g_wscaled[NCH * 16];
__device__ float g_shift[NCH];
__device__ unsigned g_ctr = 0;
// fc1 weights fp16 (hi only), layout [k'][n], k' = p*256 + c
__device__ __half g_w1hi[FLAT * 128];

// ======================= PTX helpers ==================
__device__ __forceinline__ uint32_t smem_u32(const void* p) {
    uint32_t a;
    asm("{ .reg .u64 t; cvta.to.shared.u64 t, %1; cvt.u32.u64 %0, t; }"
        : "=r"(a) : "l"(p));
    return a;
}
#define CP_ASYNC16(dst, src) \
    asm volatile("cp.async.cg.shared.global [%0], [%1], 16;" \
        :: "r"(dst), "l"(src) : "memory")
#define CP_COMMIT() asm volatile("cp.async.commit_group;" ::: "memory")
#define CP_WAIT1()  asm volatile("cp.async.wait_group 1;" ::: "memory")
#define CP_WAIT0()  asm volatile("cp.async.wait_group 0;" ::: "memory")

__device__ __forceinline__ void ldsm_x4t(uint32_t r[4], uint32_t addr) {
    asm volatile("ldmatrix.sync.aligned.m8n8.x4.trans.shared.b16 {%0,%1,%2,%3}, [%4];"
        : "=r"(r[0]), "=r"(r[1]), "=r"(r[2]), "=r"(r[3]) : "r"(addr));
}
__device__ __forceinline__ void mma16816(float& d0, float& d1, float& d2, float& d3,
                                         uint32_t a0, uint32_t a1, uint32_t a2, uint32_t a3,
                                         uint32_t b0, uint32_t b1) {
    asm volatile(
        "mma.sync.aligned.m16n8k16.row.col.f32.f16.f16.f32 "
        "{%0,%1,%2,%3}, {%4,%5,%6,%7}, {%8,%9}, {%0,%1,%2,%3};"
        : "+f"(d0), "+f"(d1), "+f"(d2), "+f"(d3)
        : "r"(a0), "r"(a1), "r"(a2), "r"(a3), "r"(b0), "r"(b1));
}
__device__ __forceinline__ uint32_t f2h2(float a, float b) {
    __half2 h = __floats2half2_rn(a, b);
    return *reinterpret_cast<uint32_t*>(&h);
}

// =========================================================================
// K1 combined: blocks 0..127 -> patch moments (last block also finalizes);
//              blocks 128..255 -> W1 prep.
// =========================================================================
__global__ __launch_bounds__(256, 2) void k_front(
    const float* __restrict__ x,
    const float* __restrict__ pw1,
    const float* __restrict__ vw1,
    const float* __restrict__ conv_w,
    const float* __restrict__ bn_gamma,
    const float* __restrict__ bn_beta)
{
    if (blockIdx.x >= NBLK_MOM) {
        // ---- W1 prep: 24 kp-rows per block, coalesced stores ----
        const int b2 = blockIdx.x - NBLK_MOM;     // 0..127
#pragma unroll
        for (int i = 0; i < 12; i++) {
            int idx = i * 256 + threadIdx.x;      // 0..3071
            int kpl = idx >> 7;                   // 0..23
            int n   = idx & 127;
            int kp  = b2 * 24 + kpl;
            int p = kp >> 8, c = kp & 255;
            int f = c * 12 + p;
            float v = (n < 64) ? pw1[(size_t)f * 64 + n]
                               : vw1[(size_t)f * 64 + (n - 64)];
            g_w1hi[(size_t)kp * 128 + n] = __float2half_rn(v);
        }
        return;
    }

    // ---- patch moments ----
    int b = blockIdx.x * 256 + threadIdx.x;
    const float* xb = x + b * 42;
    float xv[42];
#pragma unroll
    for (int i = 0; i < 42; i++) xv[i] = xb[i];

    __shared__ float red[8][NRED];
    __shared__ int lastS;
    int lane = threadIdx.x & 31;
    int warp = threadIdx.x >> 5;

    int idx = 0;
#pragma unroll
    for (int k = 0; k < 16; k++) {
        float s = 0.f;
#pragma unroll
        for (int r = 0; r < 3; r++)
#pragma unroll
            for (int c = 0; c < 4; c++)
                s += xv[(r + (k >> 2)) * 7 + (c + (k & 3))];
#pragma unroll
        for (int o = 16; o; o >>= 1) s += __shfl_xor_sync(0xffffffffu, s, o);
        if (lane == 0) red[warp][idx] = s;
        idx++;
    }
#pragma unroll
    for (int k = 0; k < 16; k++) {
#pragma unroll
        for (int l = k; l < 16; l++) {
            float s = 0.f;
#pragma unroll
            for (int r = 0; r < 3; r++)
#pragma unroll
                for (int c = 0; c < 4; c++)
                    s += xv[(r + (k >> 2)) * 7 + (c + (k & 3))] *
                         xv[(r + (l >> 2)) * 7 + (c + (l & 3))];
#pragma unroll
            for (int o = 16; o; o >>= 1) s += __shfl_xor_sync(0xffffffffu, s, o);
            if (lane == 0) red[warp][idx] = s;
            idx++;
        }
    }
    __syncthreads();
    if (threadIdx.x < NRED) {
        float s = 0.f;
#pragma unroll
        for (int w = 0; w < 8; w++) s += red[w][threadIdx.x];
        g_part[blockIdx.x][threadIdx.x] = s;
    }

    // ---- last moments block performs the BN finalize ----
    __threadfence();
    if (threadIdx.x == 0) {
        unsigned old = atomicInc(&g_ctr, NBLK_MOM - 1);   // wraps to 0 (replay-safe)
        lastS = (old == NBLK_MOM - 1);
    }
    __syncthreads();
    if (!lastS) return;

    __shared__ float S[NRED];
    int t = threadIdx.x;
    if (t < NRED) {
        float s = 0.f;
        for (int bl = 0; bl < NBLK_MOM; bl++) s += __ldcg(&g_part[bl][t]);
        S[t] = s * (1.f / (12.f * (float)BATCH));
    }
    __syncthreads();
    if (t < NCH) {
        float w[16];
#pragma unroll
        for (int i = 0; i < 16; i++) w[i] = conv_w[t * 16 + i];
        float mraw = 0.f;
#pragma unroll
        for (int i = 0; i < 16; i++) mraw += w[i] * S[i];
        float q = 0.f;
        int idx2 = 16;
#pragma unroll
        for (int k = 0; k < 16; k++)
#pragma unroll
            for (int l = k; l < 16; l++) {
                float coef = (k == l) ? (w[k] * w[l]) : (2.f * w[k] * w[l]);
                q += coef * S[idx2];
                idx2++;
            }
        float var = q - mraw * mraw;
        float a = bn_gamma[t] * rsqrtf(var + EPSV);
#pragma unroll
        for (int i = 0; i < 16; i++) g_wscaled[t * 16 + i] = a * w[i];
        g_shift[t] = bn_beta[t] - a * mraw;
    }
}

// =========================================================================
// K4: register-dataflow fused kernel (R8 main loop, verbatim).
// Warp owns m16 x n128. Per iter (K=64): conv 8 HMMA -> fc1 64 HMMA.
// Smem: B ring 3x16384 @0 | Wc hi @49152 | shift @57344
// Epilogue: h1 [128][132] f32 @0 (16B-aligned rows), h2 [128][65] @67584
// =========================================================================
#define NITER    48
#define OFF_B    0
#define OFF_WC   49152
#define OFF_SH   57344
#define SMEM_DYN 100864

__global__ __launch_bounds__(256, 2) void k_fused(
    const float* __restrict__ x,
    const float* __restrict__ pb1, const float* __restrict__ vb1,
    const float* __restrict__ pw2, const float* __restrict__ pb2,
    const float* __restrict__ pw3, const float* __restrict__ pb3,
    const float* __restrict__ vw2, const float* __restrict__ vb2,
    const float* __restrict__ vw3, const float* __restrict__ vb3,
    float* __restrict__ out)
{
    extern __shared__ char dyn_pool[];
    __shared__ float biasS[128];

    char* poolA = dyn_pool;
    const uint32_t pool_u = smem_u32(poolA);

    const int tid  = threadIdx.x;
    const int wid  = tid >> 5;
    const int lane = tid & 31;
    const int m0   = blockIdx.x * 128;

    float* shiftS = (float*)(poolA + OFF_SH);

    // ---- one-time smem fills ----
    if (tid < 64)       biasS[tid] = pb1[tid];
    else if (tid < 128) biasS[tid] = vb1[tid - 64];
    {   // folded conv weights -> Wc[k][c] fp16 (hi), swizzled rows of 512B
#pragma unroll
        for (int i = 0; i < 16; i++) {
            int idx = tid + i * 256;
            int k = idx >> 8, c = idx & 255;
            float v = g_wscaled[c * 16 + k];
            uint32_t o = (uint32_t)k * 512 + ((((uint32_t)(c >> 3)) ^ (k & 7)) << 4) + (c & 7) * 2;
            *(__half*)(poolA + OFF_WC + o) = __float2half_rn(v);
        }
    }
    shiftS[tid] = g_shift[tid];

    // ---- fc1 B cp.async lanes ----
    const int brow = tid >> 2;
    const int bq   = (tid & 3) * 4;
    const __half* gB = g_w1hi + (size_t)brow * 128 + bq * 8;
    uint32_t oBs[4];
#pragma unroll
    for (int j = 0; j < 4; j++)
        oBs[j] = (uint32_t)brow * 256 + ((((uint32_t)(bq + j)) ^ (brow & 7)) << 4);

    // ---- prologue B(0), B(1) ----
#pragma unroll
    for (int pc = 0; pc < 2; pc++) {
        const uint32_t sb = pool_u + OFF_B + pc * 16384;
        const size_t kofs = (size_t)pc * 64 * 128;
#pragma unroll
        for (int j = 0; j < 4; j++)
            CP_ASYNC16(sb + oBs[j], gB + kofs + j * 8);
        CP_COMMIT();
    }

    // ---- lane constants ----
    const int g    = lane >> 2;
    const int t2   = (lane & 3) * 2;
    const int b_kl = ((lane >> 3) & 1) * 8 + (lane & 7);
    const int b_ng = (lane >> 4);
    const uint32_t key = (uint32_t)(b_kl & 7);

    uint32_t offnp[8];
#pragma unroll
    for (int np = 0; np < 8; np++)
        offnp[np] = ((((uint32_t)(np * 2 + b_ng)) ^ key) << 4);

    // D accumulators: m16 x n128 per warp
    float d[16][4];
#pragma unroll
    for (int nt = 0; nt < 16; nt++)
#pragma unroll
        for (int q = 0; q < 4; q++) d[nt][q] = 0.f;

    __syncthreads();   // Wc / shift visible

    // x-fragment registers (fp16 hi only)
    uint32_t xhi[4];
    {
        const float* xb = x + (size_t)(m0 + wid * 16) * 42;
        int o0 = ((t2 >> 2) * 7 + (t2 & 3));
        int k1 = t2 + 8;
        int o1 = ((k1 >> 2) * 7 + (k1 & 3));
        xhi[0] = f2h2(xb[(size_t)g * 42 + o0],       xb[(size_t)g * 42 + o0 + 1]);
        xhi[1] = f2h2(xb[(size_t)(g + 8) * 42 + o0], xb[(size_t)(g + 8) * 42 + o0 + 1]);
        xhi[2] = f2h2(xb[(size_t)g * 42 + o1],       xb[(size_t)g * 42 + o1 + 1]);
        xhi[3] = f2h2(xb[(size_t)(g + 8) * 42 + o1], xb[(size_t)(g + 8) * 42 + o1 + 1]);
    }

    // ================= main loop =================
#pragma unroll 1
    for (int it = 0; it < NITER; it++) {
        CP_WAIT1();
        __syncthreads();   // B[it%3] arrived & visible

        if (it + 2 < NITER) {
            const uint32_t sb = pool_u + OFF_B + ((it + 2) % 3) * 16384;
            const size_t kofs = (size_t)(it + 2) * 64 * 128;
#pragma unroll
            for (int j = 0; j < 4; j++)
                CP_ASYNC16(sb + oBs[j], gB + kofs + j * 8);
        }
        CP_COMMIT();

        if (it > 0 && (it & 3) == 0) {
            const int p = it >> 2;
            const float* xb = x + (size_t)(m0 + wid * 16) * 42 + (p >> 2) * 7 + (p & 3);
            int o0 = ((t2 >> 2) * 7 + (t2 & 3));
            int k1 = t2 + 8;
            int o1 = ((k1 >> 2) * 7 + (k1 & 3));
            xhi[0] = f2h2(xb[(size_t)g * 42 + o0],       xb[(size_t)g * 42 + o0 + 1]);
            xhi[1] = f2h2(xb[(size_t)(g + 8) * 42 + o0], xb[(size_t)(g + 8) * 42 + o0 + 1]);
            xhi[2] = f2h2(xb[(size_t)g * 42 + o1],       xb[(size_t)g * 42 + o1 + 1]);
            xhi[3] = f2h2(xb[(size_t)(g + 8) * 42 + o1], xb[(size_t)(g + 8) * 42 + o1 + 1]);
        }

        const uint32_t sbB = pool_u + OFF_B + (it % 3) * 16384;

#pragma unroll
        for (int gg = 0; gg < 2; gg++) {
            const int grp = (it & 3) * 2 + gg;
            const int bg  = grp * 4;

            // ---- conv: batched W loads, then 4 independent MMAs ----
            uint32_t w0[4], w1[4];
            {
                uint32_t wo0 = (uint32_t)b_kl * 512 + ((((uint32_t)(bg + b_ng)) ^ key) << 4);
                uint32_t wo1 = (uint32_t)b_kl * 512 + ((((uint32_t)(bg + 2 + b_ng)) ^ key) << 4);
                ldsm_x4t(w0, pool_u + OFF_WC + wo0);
                ldsm_x4t(w1, pool_u + OFF_WC + wo1);
            }
            float cd[4][4];
#pragma unroll
            for (int nt = 0; nt < 4; nt++)
#pragma unroll
                for (int q = 0; q < 4; q++) cd[nt][q] = 0.f;
            mma16816(cd[0][0], cd[0][1], cd[0][2], cd[0][3],
                     xhi[0], xhi[1], xhi[2], xhi[3], w0[0], w0[1]);
            mma16816(cd[1][0], cd[1][1], cd[1][2], cd[1][3],
                     xhi[0], xhi[1], xhi[2], xhi[3], w0[2], w0[3]);
            mma16816(cd[2][0], cd[2][1], cd[2][2], cd[2][3],
                     xhi[0], xhi[1], xhi[2], xhi[3], w1[0], w1[1]);
            mma16816(cd[3][0], cd[3][1], cd[3][2], cd[3][3],
                     xhi[0], xhi[1], xhi[2], xhi[3], w1[2], w1[3]);

            // ---- pack: shift + ReLU + fp16 -> 2 A-fragments ----
            uint32_t afr[2][4];
#pragma unroll
            for (int pr = 0; pr < 2; pr++) {
                const float* t0 = cd[pr * 2];
                const float* t1 = cd[pr * 2 + 1];
                float2 s0 = *(const float2*)&shiftS[grp * 32 + pr * 16 + t2];
                float2 s1 = *(const float2*)&shiftS[grp * 32 + pr * 16 + 8 + t2];
                afr[pr][0] = f2h2(fmaxf(t0[0] + s0.x, 0.f), fmaxf(t0[1] + s0.y, 0.f));
                afr[pr][1] = f2h2(fmaxf(t0[2] + s0.x, 0.f), fmaxf(t0[3] + s0.y, 0.f));
                afr[pr][2] = f2h2(fmaxf(t1[0] + s1.x, 0.f), fmaxf(t1[1] + s1.y, 0.f));
                afr[pr][3] = f2h2(fmaxf(t1[2] + s1.x, 0.f), fmaxf(t1[3] + s1.y, 0.f));
            }

            // ---- fc1: 2 k16 chunks; per chunk 2 half-batches (4 ldsm + 8 mma) ----
#pragma unroll
            for (int pr = 0; pr < 2; pr++) {
                const uint32_t* af = afr[pr];
                const uint32_t kbase = sbB + (uint32_t)((gg * 2 + pr) * 16 + b_kl) * 256;
#pragma unroll
                for (int h = 0; h < 2; h++) {
                    uint32_t b4[4][4];
                    ldsm_x4t(b4[0], kbase + offnp[h * 4 + 0]);
                    ldsm_x4t(b4[1], kbase + offnp[h * 4 + 1]);
                    ldsm_x4t(b4[2], kbase + offnp[h * 4 + 2]);
                    ldsm_x4t(b4[3], kbase + offnp[h * 4 + 3]);
#pragma unroll
                    for (int j = 0; j < 4; j++) {
                        const int np = h * 4 + j;
                        mma16816(d[np * 2][0], d[np * 2][1], d[np * 2][2], d[np * 2][3],
                                 af[0], af[1], af[2], af[3], b4[j][0], b4[j][1]);
                        mma16816(d[np * 2 + 1][0], d[np * 2 + 1][1],
                                 d[np * 2 + 1][2], d[np * 2 + 1][3],
                                 af[0], af[1], af[2], af[3], b4[j][2], b4[j][3]);
                    }
                }
            }
        }
    }

    CP_WAIT0();
    __syncthreads();

    // ---------------- epilogue ----------------
    float* h1 = (float*)poolA;              // [128][132], 16B-aligned rows
    float* h2 = (float*)(poolA + 67584);    // [128][65]

    {
        const int m = wid * 16 + g;
#pragma unroll
        for (int nt = 0; nt < 16; nt++) {
            int n = nt * 8 + t2;
            h1[m * 132 + n]           = fmaxf(d[nt][0] + biasS[n], 0.f);
            h1[m * 132 + n + 1]       = fmaxf(d[nt][1] + biasS[n + 1], 0.f);
            h1[(m + 8) * 132 + n]     = fmaxf(d[nt][2] + biasS[n], 0.f);
            h1[(m + 8) * 132 + n + 1] = fmaxf(d[nt][3] + biasS[n + 1], 0.f);
        }
    }
    __syncthreads();

    // layer2 (float4-vectorized h1 reads)
#pragma unroll 1
    for (int it = 0; it < 32; it++) {
        int idx = it * 256 + tid;
        int bd = idx >> 6, o = idx & 63;
        int oo = o & 31;
        const float4* h4  = (const float4*)(h1 + bd * 132 + ((o < 32) ? 0 : 64));
        const float* wmat = (o < 32) ? pw2 : vw2;
        float s = (o < 32) ? pb2[oo] : vb2[oo];
#pragma unroll
        for (int k4 = 0; k4 < 16; k4++) {
            float4 hv = h4[k4];
            int k = k4 * 4;
            s += hv.x * wmat[k * 32 + oo];
            s += hv.y * wmat[(k + 1) * 32 + oo];
            s += hv.z * wmat[(k + 2) * 32 + oo];
            s += hv.w * wmat[(k + 3) * 32 + oo];
        }
        h2[bd * 65 + o] = fmaxf(s, 0.f);
    }
    __syncthreads();

    // layer3 + softmax / tanh
    if (tid < 128) {
        int gb = m0 + tid;
        const float* hp = h2 + tid * 65;
        float lg[7];
#pragma unroll
        for (int j = 0; j < 7; j++) {
            float s = pb3[j];
#pragma unroll
            for (int k = 0; k < 32; k++) s += hp[k] * pw3[k * 7 + j];
            lg[j] = s;
        }
        float mx = lg[0];
#pragma unroll
        for (int j = 1; j < 7; j++) mx = fmaxf(mx, lg[j]);
        float se = 0.f;
#pragma unroll
        for (int j = 0; j < 7; j++) { lg[j] = expf(lg[j] - mx); se += lg[j]; }
        float inv = 1.f / se;
#pragma unroll
        for (int j = 0; j < 7; j++) out[(size_t)gb * 7 + j] = lg[j] * inv;

        float v = vb3[0];
#pragma unroll
        for (int k = 0; k < 32; k++) v += hp[32 + k] * vw3[k];
        out[(size_t)BATCH * 7 + gb] = tanhf(v);
    }
}

// =========================================================================
extern "C" void kernel_launch(void* const* d_in, const int* in_sizes, int n_in,
                              void* d_out, int out_size)
{
    const float* x        = (const float*)d_in[0];
    const float* conv_w   = (const float*)d_in[1];
    /* conv_b cancels through batch-norm */
    const float* bn_gamma = (const float*)d_in[3];
    const float* bn_beta  = (const float*)d_in[4];
    const float* pw1 = (const float*)d_in[5];
    const float* pb1 = (const float*)d_in[6];
    const float* pw2 = (const float*)d_in[7];
    const float* pb2 = (const float*)d_in[8];
    const float* pw3 = (const float*)d_in[9];
    const float* pb3 = (const float*)d_in[10];
    const float* vw1 = (const float*)d_in[11];
    const float* vb1 = (const float*)d_in[12];
    const float* vw2 = (const float*)d_in[13];
    const float* vb2 = (const float*)d_in[14];
    const float* vw3 = (const float*)d_in[15];
    const float* vb3 = (const float*)d_in[16];
    float* out = (float*)d_out;

    cudaFuncSetAttribute(k_fused, cudaFuncAttributeMaxDynamicSharedMemorySize, SMEM_DYN);

    k_front<<<2 * NBLK_MOM, 256>>>(x, pw1, vw1, conv_w, bn_gamma, bn_beta);
    k_fused<<<BATCH / 128, 256, SMEM_DYN>>>(x, pb1, vb1, pw2, pb2, pw3, pb3,
                                            vw2, vb2, vw3, vb3, out);
}

// round 16
// speedup vs baseline: 1.8313x; 1.1045x over previous
#include <cuda_runtime.h>
#include <cuda_fp16.h>
#include <cstdint>

#define BATCH 32768
#define NCH   256
#define FLAT  3072
#define NRED  152
#define NBLK_MOM 128
#define EPSV  1e-5f

// ---------------- device scratch ----------------
__device__ float g_part[NBLK_MOM][NRED];
__device__ float g_wscaled[NCH * 16];
__device__ float g_shift[NCH];
__device__ unsigned g_ctr = 0;
// fc1 weights fp16 (hi only), layout [k'][n], k' = p*256 + c
__device__ __half g_w1hi[FLAT * 128];

// ======================= PTX helpers ==================
__device__ __forceinline__ uint32_t smem_u32(const void* p) {
    uint32_t a;
    asm("{ .reg .u64 t; cvta.to.shared.u64 t, %1; cvt.u32.u64 %0, t; }"
        : "=r"(a) : "l"(p));
    return a;
}
#define CP_ASYNC16(dst, src) \
    asm volatile("cp.async.cg.shared.global [%0], [%1], 16;" \
        :: "r"(dst), "l"(src) : "memory")
#define CP_COMMIT() asm volatile("cp.async.commit_group;" ::: "memory")
#define CP_WAIT1()  asm volatile("cp.async.wait_group 1;" ::: "memory")
#define CP_WAIT0()  asm volatile("cp.async.wait_group 0;" ::: "memory")

__device__ __forceinline__ void ldsm_x4t(uint32_t r[4], uint32_t addr) {
    asm volatile("ldmatrix.sync.aligned.m8n8.x4.trans.shared.b16 {%0,%1,%2,%3}, [%4];"
        : "=r"(r[0]), "=r"(r[1]), "=r"(r[2]), "=r"(r[3]) : "r"(addr));
}
__device__ __forceinline__ void mma16816(float& d0, float& d1, float& d2, float& d3,
                                         uint32_t a0, uint32_t a1, uint32_t a2, uint32_t a3,
                                         uint32_t b0, uint32_t b1) {
    asm volatile(
        "mma.sync.aligned.m16n8k16.row.col.f32.f16.f16.f32 "
        "{%0,%1,%2,%3}, {%4,%5,%6,%7}, {%8,%9}, {%0,%1,%2,%3};"
        : "+f"(d0), "+f"(d1), "+f"(d2), "+f"(d3)
        : "r"(a0), "r"(a1), "r"(a2), "r"(a3), "r"(b0), "r"(b1));
}
__device__ __forceinline__ uint32_t f2h2(float a, float b) {
    __half2 h = __floats2half2_rn(a, b);
    return *reinterpret_cast<uint32_t*>(&h);
}

// =========================================================================
// K1 combined: blocks 0..127 -> patch moments (last block also finalizes);
//              blocks 128..255 -> W1 prep.
// =========================================================================
__global__ __launch_bounds__(256, 2) void k_front(
    const float* __restrict__ x,
    const float* __restrict__ pw1,
    const float* __restrict__ vw1,
    const float* __restrict__ conv_w,
    const float* __restrict__ bn_gamma,
    const float* __restrict__ bn_beta)
{
    if (blockIdx.x >= NBLK_MOM) {
        const int b2 = blockIdx.x - NBLK_MOM;     // 0..127
#pragma unroll
        for (int i = 0; i < 12; i++) {
            int idx = i * 256 + threadIdx.x;
            int kpl = idx >> 7;
            int n   = idx & 127;
            int kp  = b2 * 24 + kpl;
            int p = kp >> 8, c = kp & 255;
            int f = c * 12 + p;
            float v = (n < 64) ? pw1[(size_t)f * 64 + n]
                               : vw1[(size_t)f * 64 + (n - 64)];
            g_w1hi[(size_t)kp * 128 + n] = __float2half_rn(v);
        }
        return;
    }

    // ---- patch moments ----
    int b = blockIdx.x * 256 + threadIdx.x;
    const float* xb = x + b * 42;
    float xv[42];
#pragma unroll
    for (int i = 0; i < 42; i++) xv[i] = xb[i];

    __shared__ float red[8][NRED];
    __shared__ int lastS;
    int lane = threadIdx.x & 31;
    int warp = threadIdx.x >> 5;

    int idx = 0;
#pragma unroll
    for (int k = 0; k < 16; k++) {
        float s = 0.f;
#pragma unroll
        for (int r = 0; r < 3; r++)
#pragma unroll
            for (int c = 0; c < 4; c++)
                s += xv[(r + (k >> 2)) * 7 + (c + (k & 3))];
#pragma unroll
        for (int o = 16; o; o >>= 1) s += __shfl_xor_sync(0xffffffffu, s, o);
        if (lane == 0) red[warp][idx] = s;
        idx++;
    }
#pragma unroll
    for (int k = 0; k < 16; k++) {
#pragma unroll
        for (int l = k; l < 16; l++) {
            float s = 0.f;
#pragma unroll
            for (int r = 0; r < 3; r++)
#pragma unroll
                for (int c = 0; c < 4; c++)
                    s += xv[(r + (k >> 2)) * 7 + (c + (k & 3))] *
                         xv[(r + (l >> 2)) * 7 + (c + (l & 3))];
#pragma unroll
            for (int o = 16; o; o >>= 1) s += __shfl_xor_sync(0xffffffffu, s, o);
            if (lane == 0) red[warp][idx] = s;
            idx++;
        }
    }
    __syncthreads();
    if (threadIdx.x < NRED) {
        float s = 0.f;
#pragma unroll
        for (int w = 0; w < 8; w++) s += red[w][threadIdx.x];
        g_part[blockIdx.x][threadIdx.x] = s;
    }

    __threadfence();
    if (threadIdx.x == 0) {
        unsigned old = atomicInc(&g_ctr, NBLK_MOM - 1);   // wraps (replay-safe)
        lastS = (old == NBLK_MOM - 1);
    }
    __syncthreads();
    if (!lastS) return;

    __shared__ float S[NRED];
    int t = threadIdx.x;
    if (t < NRED) {
        float s = 0.f;
        for (int bl = 0; bl < NBLK_MOM; bl++) s += __ldcg(&g_part[bl][t]);
        S[t] = s * (1.f / (12.f * (float)BATCH));
    }
    __syncthreads();
    if (t < NCH) {
        float w[16];
#pragma unroll
        for (int i = 0; i < 16; i++) w[i] = conv_w[t * 16 + i];
        float mraw = 0.f;
#pragma unroll
        for (int i = 0; i < 16; i++) mraw += w[i] * S[i];
        float q = 0.f;
        int idx2 = 16;
#pragma unroll
        for (int k = 0; k < 16; k++)
#pragma unroll
            for (int l = k; l < 16; l++) {
                float coef = (k == l) ? (w[k] * w[l]) : (2.f * w[k] * w[l]);
                q += coef * S[idx2];
                idx2++;
            }
        float var = q - mraw * mraw;
        float a = bn_gamma[t] * rsqrtf(var + EPSV);
#pragma unroll
        for (int i = 0; i < 16; i++) g_wscaled[t * 16 + i] = a * w[i];
        g_shift[t] = bn_beta[t] - a * mraw;
    }
}

// =========================================================================
// K4: fused kernel (R8/R15 main loop verbatim) + tensor-core layer2 epilogue.
// Smem: B ring 3x16384 @0 | Wc hi @49152 | shift @57344 | w2 fp16 @58368
//       epilogue: h2 [128][65] f32 @0 (B ring space, free after main loop)
// =========================================================================
#define NITER    48
#define OFF_B    0
#define OFF_WC   49152
#define OFF_SH   57344
#define OFF_W2   58368
#define SMEM_DYN 66560

__global__ __launch_bounds__(256, 2) void k_fused(
    const float* __restrict__ x,
    const float* __restrict__ pb1, const float* __restrict__ vb1,
    const float* __restrict__ pw2, const float* __restrict__ pb2,
    const float* __restrict__ pw3, const float* __restrict__ pb3,
    const float* __restrict__ vw2, const float* __restrict__ vb2,
    const float* __restrict__ vw3, const float* __restrict__ vb3,
    float* __restrict__ out)
{
    extern __shared__ char dyn_pool[];
    __shared__ float biasS[128];
    __shared__ float bias2S[64];

    char* poolA = dyn_pool;
    const uint32_t pool_u = smem_u32(poolA);

    const int tid  = threadIdx.x;
    const int wid  = tid >> 5;
    const int lane = tid & 31;
    const int m0   = blockIdx.x * 128;

    float* shiftS = (float*)(poolA + OFF_SH);

    // ---- one-time smem fills ----
    if (tid < 64)        biasS[tid] = pb1[tid];
    else if (tid < 128)  biasS[tid] = vb1[tid - 64];
    else if (tid < 192) {
        int oo = tid - 128;
        bias2S[oo] = (oo < 32) ? pb2[oo] : vb2[oo - 32];
    }
    {   // folded conv weights -> Wc[k][c] fp16 (hi), swizzled rows of 512B
#pragma unroll
        for (int i = 0; i < 16; i++) {
            int idx = tid + i * 256;
            int k = idx >> 8, c = idx & 255;
            float v = g_wscaled[c * 16 + k];
            uint32_t o = (uint32_t)k * 512 + ((((uint32_t)(c >> 3)) ^ (k & 7)) << 4) + (c & 7) * 2;
            *(__half*)(poolA + OFF_WC + o) = __float2half_rn(v);
        }
    }
    {   // layer2 weights -> w2S[k=64][n=64] fp16 (n<32 policy | n>=32 value),
        // 128B rows, XOR swizzle (same scheme as fc1 B tiles)
#pragma unroll
        for (int i = 0; i < 16; i++) {
            int idx = tid + i * 256;        // 0..4095
            int k = idx >> 6, n = idx & 63;
            float v = (n < 32) ? pw2[k * 32 + n] : vw2[k * 32 + (n - 32)];
            uint32_t o = (uint32_t)k * 128 + ((((uint32_t)(n >> 3)) ^ (k & 7)) << 4) + (n & 7) * 2;
            *(__half*)(poolA + OFF_W2 + o) = __float2half_rn(v);
        }
    }
    shiftS[tid] = g_shift[tid];

    // ---- fc1 B cp.async lanes ----
    const int brow = tid >> 2;
    const int bq   = (tid & 3) * 4;
    const __half* gB = g_w1hi + (size_t)brow * 128 + bq * 8;
    uint32_t oBs[4];
#pragma unroll
    for (int j = 0; j < 4; j++)
        oBs[j] = (uint32_t)brow * 256 + ((((uint32_t)(bq + j)) ^ (brow & 7)) << 4);

    // ---- prologue B(0), B(1) ----
#pragma unroll
    for (int pc = 0; pc < 2; pc++) {
        const uint32_t sb = pool_u + OFF_B + pc * 16384;
        const size_t kofs = (size_t)pc * 64 * 128;
#pragma unroll
        for (int j = 0; j < 4; j++)
            CP_ASYNC16(sb + oBs[j], gB + kofs + j * 8);
        CP_COMMIT();
    }

    // ---- lane constants ----
    const int g    = lane >> 2;
    const int t2   = (lane & 3) * 2;
    const int b_kl = ((lane >> 3) & 1) * 8 + (lane & 7);
    const int b_ng = (lane >> 4);
    const uint32_t key = (uint32_t)(b_kl & 7);

    uint32_t offnp[8];
#pragma unroll
    for (int np = 0; np < 8; np++)
        offnp[np] = ((((uint32_t)(np * 2 + b_ng)) ^ key) << 4);

    // D accumulators: m16 x n128 per warp
    float d[16][4];
#pragma unroll
    for (int nt = 0; nt < 16; nt++)
#pragma unroll
        for (int q = 0; q < 4; q++) d[nt][q] = 0.f;

    __syncthreads();   // Wc / shift / w2 visible

    // x-fragment registers (fp16 hi only)
    uint32_t xhi[4];
    {
        const float* xb = x + (size_t)(m0 + wid * 16) * 42;
        int o0 = ((t2 >> 2) * 7 + (t2 & 3));
        int k1 = t2 + 8;
        int o1 = ((k1 >> 2) * 7 + (k1 & 3));
        xhi[0] = f2h2(xb[(size_t)g * 42 + o0],       xb[(size_t)g * 42 + o0 + 1]);
        xhi[1] = f2h2(xb[(size_t)(g + 8) * 42 + o0], xb[(size_t)(g + 8) * 42 + o0 + 1]);
        xhi[2] = f2h2(xb[(size_t)g * 42 + o1],       xb[(size_t)g * 42 + o1 + 1]);
        xhi[3] = f2h2(xb[(size_t)(g + 8) * 42 + o1], xb[(size_t)(g + 8) * 42 + o1 + 1]);
    }

    // ================= main loop (verbatim R8/R15) =================
#pragma unroll 1
    for (int it = 0; it < NITER; it++) {
        CP_WAIT1();
        __syncthreads();   // B[it%3] arrived & visible

        if (it + 2 < NITER) {
            const uint32_t sb = pool_u + OFF_B + ((it + 2) % 3) * 16384;
            const size_t kofs = (size_t)(it + 2) * 64 * 128;
#pragma unroll
            for (int j = 0; j < 4; j++)
                CP_ASYNC16(sb + oBs[j], gB + kofs + j * 8);
        }
        CP_COMMIT();

        if (it > 0 && (it & 3) == 0) {
            const int p = it >> 2;
            const float* xb = x + (size_t)(m0 + wid * 16) * 42 + (p >> 2) * 7 + (p & 3);
            int o0 = ((t2 >> 2) * 7 + (t2 & 3));
            int k1 = t2 + 8;
            int o1 = ((k1 >> 2) * 7 + (k1 & 3));
            xhi[0] = f2h2(xb[(size_t)g * 42 + o0],       xb[(size_t)g * 42 + o0 + 1]);
            xhi[1] = f2h2(xb[(size_t)(g + 8) * 42 + o0], xb[(size_t)(g + 8) * 42 + o0 + 1]);
            xhi[2] = f2h2(xb[(size_t)g * 42 + o1],       xb[(size_t)g * 42 + o1 + 1]);
            xhi[3] = f2h2(xb[(size_t)(g + 8) * 42 + o1], xb[(size_t)(g + 8) * 42 + o1 + 1]);
        }

        const uint32_t sbB = pool_u + OFF_B + (it % 3) * 16384;

#pragma unroll
        for (int gg = 0; gg < 2; gg++) {
            const int grp = (it & 3) * 2 + gg;
            const int bg  = grp * 4;

            uint32_t w0[4], w1[4];
            {
                uint32_t wo0 = (uint32_t)b_kl * 512 + ((((uint32_t)(bg + b_ng)) ^ key) << 4);
                uint32_t wo1 = (uint32_t)b_kl * 512 + ((((uint32_t)(bg + 2 + b_ng)) ^ key) << 4);
                ldsm_x4t(w0, pool_u + OFF_WC + wo0);
                ldsm_x4t(w1, pool_u + OFF_WC + wo1);
            }
            float cd[4][4];
#pragma unroll
            for (int nt = 0; nt < 4; nt++)
#pragma unroll
                for (int q = 0; q < 4; q++) cd[nt][q] = 0.f;
            mma16816(cd[0][0], cd[0][1], cd[0][2], cd[0][3],
                     xhi[0], xhi[1], xhi[2], xhi[3], w0[0], w0[1]);
            mma16816(cd[1][0], cd[1][1], cd[1][2], cd[1][3],
                     xhi[0], xhi[1], xhi[2], xhi[3], w0[2], w0[3]);
            mma16816(cd[2][0], cd[2][1], cd[2][2], cd[2][3],
                     xhi[0], xhi[1], xhi[2], xhi[3], w1[0], w1[1]);
            mma16816(cd[3][0], cd[3][1], cd[3][2], cd[3][3],
                     xhi[0], xhi[1], xhi[2], xhi[3], w1[2], w1[3]);

            uint32_t afr[2][4];
#pragma unroll
            for (int pr = 0; pr < 2; pr++) {
                const float* t0 = cd[pr * 2];
                const float* t1 = cd[pr * 2 + 1];
                float2 s0 = *(const float2*)&shiftS[grp * 32 + pr * 16 + t2];
                float2 s1 = *(const float2*)&shiftS[grp * 32 + pr * 16 + 8 + t2];
                afr[pr][0] = f2h2(fmaxf(t0[0] + s0.x, 0.f), fmaxf(t0[1] + s0.y, 0.f));
                afr[pr][1] = f2h2(fmaxf(t0[2] + s0.x, 0.f), fmaxf(t0[3] + s0.y, 0.f));
                afr[pr][2] = f2h2(fmaxf(t1[0] + s1.x, 0.f), fmaxf(t1[1] + s1.y, 0.f));
                afr[pr][3] = f2h2(fmaxf(t1[2] + s1.x, 0.f), fmaxf(t1[3] + s1.y, 0.f));
            }

#pragma unroll
            for (int pr = 0; pr < 2; pr++) {
                const uint32_t* af = afr[pr];
                const uint32_t kbase = sbB + (uint32_t)((gg * 2 + pr) * 16 + b_kl) * 256;
#pragma unroll
                for (int h = 0; h < 2; h++) {
                    uint32_t b4[4][4];
                    ldsm_x4t(b4[0], kbase + offnp[h * 4 + 0]);
                    ldsm_x4t(b4[1], kbase + offnp[h * 4 + 1]);
                    ldsm_x4t(b4[2], kbase + offnp[h * 4 + 2]);
                    ldsm_x4t(b4[3], kbase + offnp[h * 4 + 3]);
#pragma unroll
                    for (int j = 0; j < 4; j++) {
                        const int np = h * 4 + j;
                        mma16816(d[np * 2][0], d[np * 2][1], d[np * 2][2], d[np * 2][3],
                                 af[0], af[1], af[2], af[3], b4[j][0], b4[j][1]);
                        mma16816(d[np * 2 + 1][0], d[np * 2 + 1][1],
                                 d[np * 2 + 1][2], d[np * 2 + 1][3],
                                 af[0], af[1], af[2], af[3], b4[j][2], b4[j][3]);
                    }
                }
            }
        }
    }

    CP_WAIT0();
    __syncthreads();

    // ================= epilogue: layer2 on tensor cores =================
    // h1 stays in registers: d tiles + bias1 + ReLU -> A frags; B = w2S.
    float d2[8][4];
#pragma unroll
    for (int nt = 0; nt < 8; nt++) {
        float b0 = bias2S[nt * 8 + t2];
        float b1 = bias2S[nt * 8 + t2 + 1];
        d2[nt][0] = b0; d2[nt][1] = b1; d2[nt][2] = b0; d2[nt][3] = b1;
    }
    const uint32_t w2u = pool_u + OFF_W2;
#pragma unroll
    for (int hf = 0; hf < 2; hf++) {          // 0 = policy (h1 cols 0..63), 1 = value
#pragma unroll
        for (int kk = 0; kk < 4; kk++) {
            const int tA = hf * 8 + kk * 2;
            const int n0 = tA * 8 + t2;
            const int n1 = n0 + 8;
            uint32_t a[4];
            a[0] = f2h2(fmaxf(d[tA][0] + biasS[n0], 0.f),
                        fmaxf(d[tA][1] + biasS[n0 + 1], 0.f));
            a[1] = f2h2(fmaxf(d[tA][2] + biasS[n0], 0.f),
                        fmaxf(d[tA][3] + biasS[n0 + 1], 0.f));
            a[2] = f2h2(fmaxf(d[tA + 1][0] + biasS[n1], 0.f),
                        fmaxf(d[tA + 1][1] + biasS[n1 + 1], 0.f));
            a[3] = f2h2(fmaxf(d[tA + 1][2] + biasS[n1], 0.f),
                        fmaxf(d[tA + 1][3] + biasS[n1 + 1], 0.f));
            const uint32_t kbase = w2u + (uint32_t)(kk * 16 + b_kl) * 128;
#pragma unroll
            for (int n16 = 0; n16 < 2; n16++) {
                const int np = hf * 2 + n16;
                uint32_t b4[4];
                ldsm_x4t(b4, kbase + offnp[np]);
                const int dt = np * 2;
                mma16816(d2[dt][0], d2[dt][1], d2[dt][2], d2[dt][3],
                         a[0], a[1], a[2], a[3], b4[0], b4[1]);
                mma16816(d2[dt + 1][0], d2[dt + 1][1], d2[dt + 1][2], d2[dt + 1][3],
                         a[0], a[1], a[2], a[3], b4[2], b4[3]);
            }
        }
    }

    // ReLU + store h2 (reuse B-ring smem)
    float* h2 = (float*)poolA;               // [128][65]
    {
        const int m = wid * 16 + g;
#pragma unroll
        for (int nt = 0; nt < 8; nt++) {
            int o = nt * 8 + t2;
            h2[m * 65 + o]           = fmaxf(d2[nt][0], 0.f);
            h2[m * 65 + o + 1]       = fmaxf(d2[nt][1], 0.f);
            h2[(m + 8) * 65 + o]     = fmaxf(d2[nt][2], 0.f);
            h2[(m + 8) * 65 + o + 1] = fmaxf(d2[nt][3], 0.f);
        }
    }
    __syncthreads();

    // layer3 + softmax / tanh
    if (tid < 128) {
        int gb = m0 + tid;
        const float* hp = h2 + tid * 65;
        float lg[7];
#pragma unroll
        for (int j = 0; j < 7; j++) {
            float s = pb3[j];
#pragma unroll
            for (int k = 0; k < 32; k++) s += hp[k] * pw3[k * 7 + j];
            lg[j] = s;
        }
        float mx = lg[0];
#pragma unroll
        for (int j = 1; j < 7; j++) mx = fmaxf(mx, lg[j]);
        float se = 0.f;
#pragma unroll
        for (int j = 0; j < 7; j++) { lg[j] = expf(lg[j] - mx); se += lg[j]; }
        float inv = 1.f / se;
#pragma unroll
        for (int j = 0; j < 7; j++) out[(size_t)gb * 7 + j] = lg[j] * inv;

        float v = vb3[0];
#pragma unroll
        for (int k = 0; k < 32; k++) v += hp[32 + k] * vw3[k];
        out[(size_t)BATCH * 7 + gb] = tanhf(v);
    }
}

// =========================================================================
extern "C" void kernel_launch(void* const* d_in, const int* in_sizes, int n_in,
                              void* d_out, int out_size)
{
    const float* x        = (const float*)d_in[0];
    const float* conv_w   = (const float*)d_in[1];
    /* conv_b cancels through batch-norm */
    const float* bn_gamma = (const float*)d_in[3];
    const float* bn_beta  = (const float*)d_in[4];
    const float* pw1 = (const float*)d_in[5];
    const float* pb1 = (const float*)d_in[6];
    const float* pw2 = (const float*)d_in[7];
    const float* pb2 = (const float*)d_in[8];
    const float* pw3 = (const float*)d_in[9];
    const float* pb3 = (const float*)d_in[10];
    const float* vw1 = (const float*)d_in[11];
    const float* vb1 = (const float*)d_in[12];
    const float* vw2 = (const float*)d_in[13];
    const float* vb2 = (const float*)d_in[14];
    const float* vw3 = (const float*)d_in[15];
    const float* vb3 = (const float*)d_in[16];
    float* out = (float*)d_out;

    cudaFuncSetAttribute(k_fused, cudaFuncAttributeMaxDynamicSharedMemorySize, SMEM_DYN);

    k_front<<<2 * NBLK_MOM, 256>>>(x, pw1, vw1, conv_w, bn_gamma, bn_beta);
    k_fused<<<BATCH / 128, 256, SMEM_DYN>>>(x, pb1, vb1, pw2, pb2, pw3, pb3,
                                            vw2, vb2, vw3, vb3, out);
}